// round 16
// baseline (speedup 1.0000x reference)
#include <cuda_runtime.h>
#include <cuda_bf16.h>
#include <cuda_fp16.h>
#include <cstdint>

#define NN 100000
#define NE 320000
#define DIN 256
#define DH  64
#define DO  4

// Scratch (device globals; no allocation allowed)
__device__ float g_y[NN * 128];        // x @ [W1_l | W1_r]
__device__ float g_z[NN * 8];
// merged zeroed scratch: [agg1: NN*64][agg2: NN*4][deg: NN]  -> ONE memset
__device__ float g_scratch[NN * 69];
#define AGG1 (g_scratch)
#define AGG2 (g_scratch + (size_t)NN * 64)
#define DEGA (g_scratch + (size_t)NN * 68)
// B fragments (fp16, single term), fragment-major:
// [(ntile*16+kstep)*32 + lane] = {bh0, bh1}. k within each 16-tile PERMUTED:
// logical slots {2q,2q+1,2q+8,2q+9} hold original k {4q..4q+3} so the x side
// loads one contiguous float4 per row.
__device__ uint2 g_Bfrag[16 * 16 * 32];

// pack two f32 -> f16x2 (elem0 = low 16 bits)
#define PACK_F16X2(d, e0, e1) \
    asm("cvt.rn.f16x2.f32 %0, %1, %2;" : "=r"(d) : "f"(e1), "f"(e0))

__device__ __forceinline__ void mma16816(float* d, const uint32_t* a,
                                         uint32_t b0, uint32_t b1) {
    asm volatile(
        "mma.sync.aligned.m16n8k16.row.col.f32.f16.f16.f32 "
        "{%0,%1,%2,%3},{%4,%5,%6,%7},{%8,%9},{%0,%1,%2,%3};"
        : "+f"(d[0]), "+f"(d[1]), "+f"(d[2]), "+f"(d[3])
        : "r"(a[0]), "r"(a[1]), "r"(a[2]), "r"(a[3]), "r"(b0), "r"(b1));
}

// Build hi/lo fp16 a-frags from two contiguous float4 rows (r and r+8).
// xh = fp16(x); xl = fp16(x - float(xh)) -> xh+xl represents x to ~2^-22.
__device__ __forceinline__ void build_frag4(uint32_t* ah, uint32_t* al,
                                            float4 a, float4 b) {
    float h0, h1;
    h0 = __half2float(__float2half_rn(a.x));
    h1 = __half2float(__float2half_rn(a.y));
    PACK_F16X2(ah[0], h0, h1); PACK_F16X2(al[0], a.x - h0, a.y - h1);
    h0 = __half2float(__float2half_rn(b.x));
    h1 = __half2float(__float2half_rn(b.y));
    PACK_F16X2(ah[1], h0, h1); PACK_F16X2(al[1], b.x - h0, b.y - h1);
    h0 = __half2float(__float2half_rn(a.z));
    h1 = __half2float(__float2half_rn(a.w));
    PACK_F16X2(ah[2], h0, h1); PACK_F16X2(al[2], a.z - h0, a.w - h1);
    h0 = __half2float(__float2half_rn(b.z));
    h1 = __half2float(__float2half_rn(b.w));
    PACK_F16X2(ah[3], h0, h1); PACK_F16X2(al[3], b.z - h0, b.w - h1);
}

// ---------------- prep: W -> fp16 mma fragments (k-permuted) ----------------
__global__ void prep_bfrag_kernel(const float* __restrict__ Wl,
                                  const float* __restrict__ Wr) {
    int t = blockIdx.x * blockDim.x + threadIdx.x;   // 8192
    if (t >= 16 * 16 * 32) return;
    int lane = t & 31;
    int ks = (t >> 5) & 15;
    int nt = t >> 9;
    int n = nt * 8 + (lane >> 2);
    int q = lane & 3;
    int k = ks * 16 + q * 4;       // permuted: 4 consecutive original k per lane
    const float* W = (n < DH) ? Wl : Wr;
    int nn = (n < DH) ? n : n - DH;
    float v[4] = { W[(k)     * DH + nn], W[(k + 1) * DH + nn],
                   W[(k + 2) * DH + nn], W[(k + 3) * DH + nn] };
    uint2 o;
    PACK_F16X2(o.x, v[0], v[1]);   // logical slots (2q, 2q+1)
    PACK_F16X2(o.y, v[2], v[3]);   // logical slots (2q+8, 2q+9)
    g_Bfrag[t] = o;
}

// ---------------- GEMM1 via mma.sync fp16 2-term x-split: y = x @ Wcat ----------------
// 512 threads, block 128 rows x 128 cols; 16 warps = 8 M-tiles x 2 N-halves,
// warp tile M=16 x N=64. B fragments (64 KB, fp16) staged in dynamic smem
// once; inner loop: 2 MMAs per nt (xh*W + xl*W). 1 block/SM.
__global__ __launch_bounds__(512, 1) void gemm1_hmma_kernel(const float* __restrict__ x, int N) {
    extern __shared__ uint2 sB[];    // [16nt][16ks][32lane] = 8192 uint2 = 64 KB
    const int tid = threadIdx.x;
    const int wid = tid >> 5;
    const int lane = tid & 31;
    const int g = lane >> 2;       // row within tile
    const int q = lane & 3;        // k / n pos
    const int h = wid >> 3;        // N-half
    const int mw = wid & 7;        // M-tile

    // stage all B fragments into smem (coalesced; g_Bfrag is L2-resident)
#pragma unroll
    for (int i = 0; i < 16; ++i)
        sB[i * 512 + tid] = g_Bfrag[i * 512 + tid];

    const int rowbase = blockIdx.x * 128 + mw * 16;
    const int r0 = rowbase + g;
    const int r1 = r0 + 8;
    const bool v0 = r0 < N;
    const bool v1 = r1 < N;
    const float* xr0 = x + (size_t)r0 * DIN;
    const float* xr1 = x + (size_t)r1 * DIN;

    float acc[8][4];
#pragma unroll
    for (int nt = 0; nt < 8; nt++)
#pragma unroll
        for (int j = 0; j < 4; j++) acc[nt][j] = 0.0f;

    const float4 Z4 = make_float4(0.f, 0.f, 0.f, 0.f);
    float4 p0, p1;
    {
        const int k0 = q * 4;
        p0 = v0 ? *reinterpret_cast<const float4*>(xr0 + k0) : Z4;
        p1 = v1 ? *reinterpret_cast<const float4*>(xr1 + k0) : Z4;
    }

    __syncthreads();   // B staged

#pragma unroll
    for (int ks = 0; ks < 16; ++ks) {
        uint32_t ah[4], al[4];
        build_frag4(ah, al, p0, p1);

        if (ks < 15) {   // prefetch next k-step; overlaps with MMA burst below
            const int kn = (ks + 1) * 16 + q * 4;
            p0 = v0 ? *reinterpret_cast<const float4*>(xr0 + kn) : Z4;
            p1 = v1 ? *reinterpret_cast<const float4*>(xr1 + kn) : Z4;
        }

#pragma unroll
        for (int nt = 0; nt < 8; ++nt) {
            uint2 b = sB[((h * 8 + nt) * 16 + ks) * 32 + lane];
            mma16816(acc[nt], ah, b.x, b.y);   // xh * W
            mma16816(acc[nt], al, b.x, b.y);   // xl * W
        }
    }

    if (v0) {
        float* dp = &g_y[(size_t)r0 * 128 + h * 64];
#pragma unroll
        for (int nt = 0; nt < 8; ++nt)
            *reinterpret_cast<float2*>(dp + nt * 8 + q * 2) = make_float2(acc[nt][0], acc[nt][1]);
    }
    if (v1) {
        float* dp = &g_y[(size_t)r1 * 128 + h * 64];
#pragma unroll
        for (int nt = 0; nt < 8; ++nt)
            *reinterpret_cast<float2*>(dp + nt * 8 + q * 2) = make_float2(acc[nt][2], acc[nt][3]);
    }
}

// ---------------- scatter 1 (+ fused degree): agg1[dst] += y_l[src]; deg[dst] += 1 ----------------
__global__ void scatter1_kernel(const int* __restrict__ src,
                                const int* __restrict__ dst, int E) {
    int t = blockIdx.x * blockDim.x + threadIdx.x;
    if (t < E * 16) {
        int e = t >> 4;
        int cq = t & 15;
        int c = cq * 4;
        int s = __ldg(&src[e]);
        int d = __ldg(&dst[e]);
        float4 v = *reinterpret_cast<const float4*>(&g_y[(size_t)s * 128 + c]);
        asm volatile("red.global.add.v4.f32 [%0], {%1, %2, %3, %4};"
                     :: "l"(&AGG1[(size_t)d * 64 + c]),
                        "f"(v.x), "f"(v.y), "f"(v.z), "f"(v.w)
                     : "memory");
        if (cq == 0) {
            asm volatile("red.global.add.f32 [%0], %1;"
                         :: "l"(&DEGA[d]), "f"(1.0f) : "memory");
        }
    }
}

// ---------------- node 1: TWO threads per node (half = tid&1 handles 32 ch) ----------------
// relu(v*scale)=scale*relu(v): single pass computes ss and z partials; pair
// combines via SYMMETRIC shfl_xor(1) (same logical slot on both lanes).
// Inactive tail lanes clamp n (no early return) so full-mask shuffles are safe.
__global__ __launch_bounds__(512) void node1_kernel(
    const float* __restrict__ b1,
    const float* __restrict__ W2l,   // [64,4]
    const float* __restrict__ W2r,   // [64,4]
    int N)
{
    __shared__ float ws[64][8];
    __shared__ float b1s[64];
    int tid = threadIdx.x;
    {
        int k = tid >> 3, j = tid & 7;
        ws[k][j] = (j < 4) ? W2l[k * 4 + j] : W2r[k * 4 + (j - 4)];
    }
    if (tid < 64) b1s[tid] = b1[tid];
    __syncthreads();

    int n0 = blockIdx.x * 256 + (tid >> 1);
    int half = tid & 1;
    int n = min(n0, N - 1);            // clamp: keep all lanes shuffle-active

    float invd = 1.0f / fmaxf(DEGA[n], 1.0f);
    const int cbase = half * 8;          // float4-chunk base (8 chunks = 32 ch)
    const float4* ar = reinterpret_cast<const float4*>(&AGG1[(size_t)n * 64]) + cbase;
    const float4* yr = reinterpret_cast<const float4*>(&g_y[(size_t)n * 128 + 64]) + cbase;

    float z[8];
#pragma unroll
    for (int j = 0; j < 8; j++) z[j] = 0.0f;
    float ss = 0.0f;

#pragma unroll
    for (int i = 0; i < 8; ++i) {
        float4 a = ar[i];
        float4 y = yr[i];
        int c = (cbase + i) * 4;
        float v[4];
        v[0] = fmaf(a.x, invd, y.x + b1s[c + 0]);
        v[1] = fmaf(a.y, invd, y.y + b1s[c + 1]);
        v[2] = fmaf(a.z, invd, y.z + b1s[c + 2]);
        v[3] = fmaf(a.w, invd, y.w + b1s[c + 3]);
#pragma unroll
        for (int j2 = 0; j2 < 4; ++j2) {
            ss = fmaf(v[j2], v[j2], ss);
            float r = fmaxf(v[j2], 0.0f);
            const float4 w0 = *reinterpret_cast<const float4*>(&ws[c + j2][0]);
            const float4 w1 = *reinterpret_cast<const float4*>(&ws[c + j2][4]);
            z[0] = fmaf(r, w0.x, z[0]);
            z[1] = fmaf(r, w0.y, z[1]);
            z[2] = fmaf(r, w0.z, z[2]);
            z[3] = fmaf(r, w0.w, z[3]);
            z[4] = fmaf(r, w1.x, z[4]);
            z[5] = fmaf(r, w1.y, z[5]);
            z[6] = fmaf(r, w1.z, z[6]);
            z[7] = fmaf(r, w1.w, z[7]);
        }
    }

    // pair combine — SYMMETRIC: both lanes exchange the SAME logical slot j
    ss += __shfl_xor_sync(0xFFFFFFFFu, ss, 1);
#pragma unroll
    for (int j = 0; j < 8; ++j)
        z[j] += __shfl_xor_sync(0xFFFFFFFFu, z[j], 1);

    if (n0 < N) {
        float scale = 1.0f / fmaxf(sqrtf(ss), 1e-12f);
        int j0 = half * 4;   // each half writes its own float4 of z
        *reinterpret_cast<float4*>(&g_z[(size_t)n0 * 8 + j0]) =
            make_float4(z[j0 + 0] * scale, z[j0 + 1] * scale,
                        z[j0 + 2] * scale, z[j0 + 3] * scale);
    }
}

// ---------------- scatter 2 ----------------
__global__ void scatter2_kernel(const int* __restrict__ src,
                                const int* __restrict__ dst, int E) {
    int e = blockIdx.x * blockDim.x + threadIdx.x;
    if (e < E) {
        int s = __ldg(&src[e]);
        int d = __ldg(&dst[e]);
        float4 zl = *reinterpret_cast<const float4*>(&g_z[(size_t)s * 8]);
        asm volatile("red.global.add.v4.f32 [%0], {%1, %2, %3, %4};"
                     :: "l"(&AGG2[(size_t)d * 4]),
                        "f"(zl.x), "f"(zl.y), "f"(zl.z), "f"(zl.w)
                     : "memory");
    }
}

// ---------------- final ----------------
__global__ void node2_kernel(const float* __restrict__ b2,
                             float* __restrict__ out, int N) {
    int n = blockIdx.x * blockDim.x + threadIdx.x;
    if (n >= N) return;
    float invd = 1.0f / fmaxf(DEGA[n], 1.0f);
    float4 a  = *reinterpret_cast<const float4*>(&AGG2[(size_t)n * 4]);
    float4 zr = *reinterpret_cast<const float4*>(&g_z[(size_t)n * 8 + 4]);
    float v0 = a.x * invd + b2[0] + zr.x;
    float v1 = a.y * invd + b2[1] + zr.y;
    float v2 = a.z * invd + b2[2] + zr.z;
    float v3 = a.w * invd + b2[3] + zr.w;
    float ss = v0 * v0 + v1 * v1 + v2 * v2 + v3 * v3;
    float scale = 1.0f / fmaxf(sqrtf(ss), 1e-12f);
    *reinterpret_cast<float4*>(&out[(size_t)n * 4]) =
        make_float4(v0 * scale, v1 * scale, v2 * scale, v3 * scale);
}

extern "C" void kernel_launch(void* const* d_in, const int* in_sizes, int n_in,
                              void* d_out, int out_size) {
    const float* x   = (const float*)d_in[0];
    const int*   ei  = (const int*)  d_in[1];
    const float* W1l = (const float*)d_in[2];
    const float* b1l = (const float*)d_in[3];
    const float* W1r = (const float*)d_in[4];
    const float* W2l = (const float*)d_in[5];
    const float* b2l = (const float*)d_in[6];
    const float* W2r = (const float*)d_in[7];

    const int N = in_sizes[0] / DIN;
    const int E = in_sizes[1] / 2;
    const int* src = ei;
    const int* dst = ei + E;

    const int SMEM_B = 16 * 16 * 32 * sizeof(uint2);   // 64 KB
    cudaFuncSetAttribute(gemm1_hmma_kernel,
                         cudaFuncAttributeMaxDynamicSharedMemorySize, SMEM_B);

    void* p_scratch;
    cudaGetSymbolAddress(&p_scratch, g_scratch);
    cudaMemsetAsync(p_scratch, 0, sizeof(float) * (size_t)NN * 69);

    prep_bfrag_kernel<<<32, 256>>>(W1l, W1r);
    gemm1_hmma_kernel<<<(N + 127) / 128, 512, SMEM_B>>>(x, N);
    {
        long long tot = (long long)E * 16;
        int blocks = (int)((tot + 255) / 256);
        scatter1_kernel<<<blocks, 256>>>(src, dst, E);
    }
    node1_kernel<<<(N + 255) / 256, 512>>>(b1l, W2l, W2r, N);
    scatter2_kernel<<<(E + 255) / 256, 256>>>(src, dst, E);
    node2_kernel<<<(N + 255) / 256, 256>>>(b2l, (float*)d_out, N);
}

// round 17
// speedup vs baseline: 1.1086x; 1.1086x over previous
#include <cuda_runtime.h>
#include <cuda_bf16.h>
#include <cuda_fp16.h>
#include <cstdint>

#define NN 100000
#define NE 320000
#define DIN 256
#define DH  64
#define DO  4

// Scratch (device globals; no allocation allowed)
__device__ float g_y[NN * 128];        // x @ [W1_l | W1_r]
__device__ float g_z[NN * 8];
// merged zeroed scratch: [agg1: NN*64][agg2: NN*4][deg: NN]  -> ONE memset
__device__ float g_scratch[NN * 69];
#define AGG1 (g_scratch)
#define AGG2 (g_scratch + (size_t)NN * 64)
#define DEGA (g_scratch + (size_t)NN * 68)
// B fragments (fp16, single term), fragment-major:
// [(ntile*16+kstep)*32 + lane] = {bh0, bh1}. k within each 16-tile PERMUTED:
// logical slots {2q,2q+1,2q+8,2q+9} hold original k {4q..4q+3} so the x side
// loads one contiguous float4 per row.
__device__ uint2 g_Bfrag[16 * 16 * 32];

// pack two f32 -> f16x2 (elem0 = low 16 bits)
#define PACK_F16X2(d, e0, e1) \
    asm("cvt.rn.f16x2.f32 %0, %1, %2;" : "=r"(d) : "f"(e1), "f"(e0))

__device__ __forceinline__ void mma16816(float* d, const uint32_t* a,
                                         uint32_t b0, uint32_t b1) {
    asm volatile(
        "mma.sync.aligned.m16n8k16.row.col.f32.f16.f16.f32 "
        "{%0,%1,%2,%3},{%4,%5,%6,%7},{%8,%9},{%0,%1,%2,%3};"
        : "+f"(d[0]), "+f"(d[1]), "+f"(d[2]), "+f"(d[3])
        : "r"(a[0]), "r"(a[1]), "r"(a[2]), "r"(a[3]), "r"(b0), "r"(b1));
}

// Build hi/lo fp16 a-frags from two contiguous float4 rows (r and r+8).
// xh = fp16(x); xl = fp16(x - float(xh)) -> xh+xl represents x to ~2^-22.
__device__ __forceinline__ void build_frag4(uint32_t* ah, uint32_t* al,
                                            float4 a, float4 b) {
    float h0, h1;
    h0 = __half2float(__float2half_rn(a.x));
    h1 = __half2float(__float2half_rn(a.y));
    PACK_F16X2(ah[0], h0, h1); PACK_F16X2(al[0], a.x - h0, a.y - h1);
    h0 = __half2float(__float2half_rn(b.x));
    h1 = __half2float(__float2half_rn(b.y));
    PACK_F16X2(ah[1], h0, h1); PACK_F16X2(al[1], b.x - h0, b.y - h1);
    h0 = __half2float(__float2half_rn(a.z));
    h1 = __half2float(__float2half_rn(a.w));
    PACK_F16X2(ah[2], h0, h1); PACK_F16X2(al[2], a.z - h0, a.w - h1);
    h0 = __half2float(__float2half_rn(b.z));
    h1 = __half2float(__float2half_rn(b.w));
    PACK_F16X2(ah[3], h0, h1); PACK_F16X2(al[3], b.z - h0, b.w - h1);
}

// ---------------- prep: W -> fp16 mma fragments (k-permuted) ----------------
__global__ void prep_bfrag_kernel(const float* __restrict__ Wl,
                                  const float* __restrict__ Wr) {
    int t = blockIdx.x * blockDim.x + threadIdx.x;   // 8192
    if (t >= 16 * 16 * 32) return;
    int lane = t & 31;
    int ks = (t >> 5) & 15;
    int nt = t >> 9;
    int n = nt * 8 + (lane >> 2);
    int q = lane & 3;
    int k = ks * 16 + q * 4;       // permuted: 4 consecutive original k per lane
    const float* W = (n < DH) ? Wl : Wr;
    int nn = (n < DH) ? n : n - DH;
    float v[4] = { W[(k)     * DH + nn], W[(k + 1) * DH + nn],
                   W[(k + 2) * DH + nn], W[(k + 3) * DH + nn] };
    uint2 o;
    PACK_F16X2(o.x, v[0], v[1]);   // logical slots (2q, 2q+1)
    PACK_F16X2(o.y, v[2], v[3]);   // logical slots (2q+8, 2q+9)
    g_Bfrag[t] = o;
}

// ---------------- GEMM1 via mma.sync fp16 2-term x-split: y = x @ Wcat ----------------
// 512 threads, block 128 rows x 128 cols; 16 warps = 8 M-tiles x 2 N-halves,
// warp tile M=16 x N=64. B fragments (64 KB, fp16) staged in dynamic smem
// once. x loads DOUBLE-BUFFERED two k-steps ahead (4 LDG.128 in flight) to
// raise DRAM MLP — the kernel is x-latency bound. 1 block/SM.
__global__ __launch_bounds__(512, 1) void gemm1_hmma_kernel(const float* __restrict__ x, int N) {
    extern __shared__ uint2 sB[];    // [16nt][16ks][32lane] = 8192 uint2 = 64 KB
    const int tid = threadIdx.x;
    const int wid = tid >> 5;
    const int lane = tid & 31;
    const int g = lane >> 2;       // row within tile
    const int q = lane & 3;        // k / n pos
    const int h = wid >> 3;        // N-half
    const int mw = wid & 7;        // M-tile

    // stage all B fragments into smem (coalesced; g_Bfrag is L2-resident)
#pragma unroll
    for (int i = 0; i < 16; ++i)
        sB[i * 512 + tid] = g_Bfrag[i * 512 + tid];

    const int rowbase = blockIdx.x * 128 + mw * 16;
    const int r0 = rowbase + g;
    const int r1 = r0 + 8;
    const bool v0 = r0 < N;
    const bool v1 = r1 < N;
    const float* xr0 = x + (size_t)r0 * DIN;
    const float* xr1 = x + (size_t)r1 * DIN;

    float acc[8][4];
#pragma unroll
    for (int nt = 0; nt < 8; nt++)
#pragma unroll
        for (int j = 0; j < 4; j++) acc[nt][j] = 0.0f;

    const float4 Z4 = make_float4(0.f, 0.f, 0.f, 0.f);
    float4 pf0[2], pf1[2];   // double-buffered x rows (ks and ks+1 in flight)
    {
        const int ka = q * 4;
        const int kb = 16 + q * 4;
        pf0[0] = v0 ? *reinterpret_cast<const float4*>(xr0 + ka) : Z4;
        pf1[0] = v1 ? *reinterpret_cast<const float4*>(xr1 + ka) : Z4;
        pf0[1] = v0 ? *reinterpret_cast<const float4*>(xr0 + kb) : Z4;
        pf1[1] = v1 ? *reinterpret_cast<const float4*>(xr1 + kb) : Z4;
    }

    __syncthreads();   // B staged

#pragma unroll
    for (int ks = 0; ks < 16; ++ks) {
        const int b = ks & 1;
        uint32_t ah[4], al[4];
        build_frag4(ah, al, pf0[b], pf1[b]);

        if (ks < 14) {   // refill freed buffer with k-step ks+2
            const int kn = (ks + 2) * 16 + q * 4;
            pf0[b] = v0 ? *reinterpret_cast<const float4*>(xr0 + kn) : Z4;
            pf1[b] = v1 ? *reinterpret_cast<const float4*>(xr1 + kn) : Z4;
        }

#pragma unroll
        for (int nt = 0; nt < 8; ++nt) {
            uint2 bb = sB[((h * 8 + nt) * 16 + ks) * 32 + lane];
            mma16816(acc[nt], ah, bb.x, bb.y);   // xh * W
            mma16816(acc[nt], al, bb.x, bb.y);   // xl * W
        }
    }

    if (v0) {
        float* dp = &g_y[(size_t)r0 * 128 + h * 64];
#pragma unroll
        for (int nt = 0; nt < 8; ++nt)
            *reinterpret_cast<float2*>(dp + nt * 8 + q * 2) = make_float2(acc[nt][0], acc[nt][1]);
    }
    if (v1) {
        float* dp = &g_y[(size_t)r1 * 128 + h * 64];
#pragma unroll
        for (int nt = 0; nt < 8; ++nt)
            *reinterpret_cast<float2*>(dp + nt * 8 + q * 2) = make_float2(acc[nt][2], acc[nt][3]);
    }
}

// ---------------- scatter 1 (+ fused degree): agg1[dst] += y_l[src]; deg[dst] += 1 ----------------
__global__ void scatter1_kernel(const int* __restrict__ src,
                                const int* __restrict__ dst, int E) {
    int t = blockIdx.x * blockDim.x + threadIdx.x;
    if (t < E * 16) {
        int e = t >> 4;
        int cq = t & 15;
        int c = cq * 4;
        int s = __ldg(&src[e]);
        int d = __ldg(&dst[e]);
        float4 v = *reinterpret_cast<const float4*>(&g_y[(size_t)s * 128 + c]);
        asm volatile("red.global.add.v4.f32 [%0], {%1, %2, %3, %4};"
                     :: "l"(&AGG1[(size_t)d * 64 + c]),
                        "f"(v.x), "f"(v.y), "f"(v.z), "f"(v.w)
                     : "memory");
        if (cq == 0) {
            asm volatile("red.global.add.f32 [%0], %1;"
                         :: "l"(&DEGA[d]), "f"(1.0f) : "memory");
        }
    }
}

// ---------------- node 1: thread-per-node, single pass (R14 version) ----------------
__global__ __launch_bounds__(256) void node1_kernel(
    const float* __restrict__ b1,
    const float* __restrict__ W2l,   // [64,4]
    const float* __restrict__ W2r,   // [64,4]
    int N)
{
    __shared__ float ws[64][8];
    __shared__ float b1s[64];
    int tid = threadIdx.x;
#pragma unroll
    for (int t = tid; t < 512; t += 256) {
        int k = t >> 3, j = t & 7;
        ws[k][j] = (j < 4) ? W2l[k * 4 + j] : W2r[k * 4 + (j - 4)];
    }
    if (tid < 64) b1s[tid] = b1[tid];
    __syncthreads();

    int n = blockIdx.x * 256 + tid;
    if (n >= N) return;

    float invd = 1.0f / fmaxf(DEGA[n], 1.0f);
    const float4* ar = reinterpret_cast<const float4*>(&AGG1[(size_t)n * 64]);
    const float4* yr = reinterpret_cast<const float4*>(&g_y[(size_t)n * 128 + 64]);

    float z[8];
#pragma unroll
    for (int j = 0; j < 8; j++) z[j] = 0.0f;
    float ss = 0.0f;

#pragma unroll
    for (int c0 = 0; c0 < 16; c0 += 8) {
        float4 A[8], Y[8];
#pragma unroll
        for (int i = 0; i < 8; ++i) { A[i] = ar[c0 + i]; Y[i] = yr[c0 + i]; }
#pragma unroll
        for (int i = 0; i < 8; ++i) {
            int c = c0 + i;
            float v[4];
            v[0] = fmaf(A[i].x, invd, Y[i].x + b1s[c * 4 + 0]);
            v[1] = fmaf(A[i].y, invd, Y[i].y + b1s[c * 4 + 1]);
            v[2] = fmaf(A[i].z, invd, Y[i].z + b1s[c * 4 + 2]);
            v[3] = fmaf(A[i].w, invd, Y[i].w + b1s[c * 4 + 3]);
#pragma unroll
            for (int j2 = 0; j2 < 4; ++j2) {
                ss = fmaf(v[j2], v[j2], ss);
                float r = fmaxf(v[j2], 0.0f);
                const float4 w0 = *reinterpret_cast<const float4*>(&ws[c * 4 + j2][0]);
                const float4 w1 = *reinterpret_cast<const float4*>(&ws[c * 4 + j2][4]);
                z[0] = fmaf(r, w0.x, z[0]);
                z[1] = fmaf(r, w0.y, z[1]);
                z[2] = fmaf(r, w0.z, z[2]);
                z[3] = fmaf(r, w0.w, z[3]);
                z[4] = fmaf(r, w1.x, z[4]);
                z[5] = fmaf(r, w1.y, z[5]);
                z[6] = fmaf(r, w1.z, z[6]);
                z[7] = fmaf(r, w1.w, z[7]);
            }
        }
    }

    float scale = 1.0f / fmaxf(sqrtf(ss), 1e-12f);
    float* zp = &g_z[(size_t)n * 8];
    *reinterpret_cast<float4*>(zp) =
        make_float4(z[0] * scale, z[1] * scale, z[2] * scale, z[3] * scale);
    *reinterpret_cast<float4*>(zp + 4) =
        make_float4(z[4] * scale, z[5] * scale, z[6] * scale, z[7] * scale);
}

// ---------------- scatter 2 ----------------
__global__ void scatter2_kernel(const int* __restrict__ src,
                                const int* __restrict__ dst, int E) {
    int e = blockIdx.x * blockDim.x + threadIdx.x;
    if (e < E) {
        int s = __ldg(&src[e]);
        int d = __ldg(&dst[e]);
        float4 zl = *reinterpret_cast<const float4*>(&g_z[(size_t)s * 8]);
        asm volatile("red.global.add.v4.f32 [%0], {%1, %2, %3, %4};"
                     :: "l"(&AGG2[(size_t)d * 4]),
                        "f"(zl.x), "f"(zl.y), "f"(zl.z), "f"(zl.w)
                     : "memory");
    }
}

// ---------------- final ----------------
__global__ void node2_kernel(const float* __restrict__ b2,
                             float* __restrict__ out, int N) {
    int n = blockIdx.x * blockDim.x + threadIdx.x;
    if (n >= N) return;
    float invd = 1.0f / fmaxf(DEGA[n], 1.0f);
    float4 a  = *reinterpret_cast<const float4*>(&AGG2[(size_t)n * 4]);
    float4 zr = *reinterpret_cast<const float4*>(&g_z[(size_t)n * 8 + 4]);
    float v0 = a.x * invd + b2[0] + zr.x;
    float v1 = a.y * invd + b2[1] + zr.y;
    float v2 = a.z * invd + b2[2] + zr.z;
    float v3 = a.w * invd + b2[3] + zr.w;
    float ss = v0 * v0 + v1 * v1 + v2 * v2 + v3 * v3;
    float scale = 1.0f / fmaxf(sqrtf(ss), 1e-12f);
    *reinterpret_cast<float4*>(&out[(size_t)n * 4]) =
        make_float4(v0 * scale, v1 * scale, v2 * scale, v3 * scale);
}

extern "C" void kernel_launch(void* const* d_in, const int* in_sizes, int n_in,
                              void* d_out, int out_size) {
    const float* x   = (const float*)d_in[0];
    const int*   ei  = (const int*)  d_in[1];
    const float* W1l = (const float*)d_in[2];
    const float* b1l = (const float*)d_in[3];
    const float* W1r = (const float*)d_in[4];
    const float* W2l = (const float*)d_in[5];
    const float* b2l = (const float*)d_in[6];
    const float* W2r = (const float*)d_in[7];

    const int N = in_sizes[0] / DIN;
    const int E = in_sizes[1] / 2;
    const int* src = ei;
    const int* dst = ei + E;

    const int SMEM_B = 16 * 16 * 32 * sizeof(uint2);   // 64 KB
    cudaFuncSetAttribute(gemm1_hmma_kernel,
                         cudaFuncAttributeMaxDynamicSharedMemorySize, SMEM_B);

    void* p_scratch;
    cudaGetSymbolAddress(&p_scratch, g_scratch);
    cudaMemsetAsync(p_scratch, 0, sizeof(float) * (size_t)NN * 69);

    prep_bfrag_kernel<<<32, 256>>>(W1l, W1r);
    gemm1_hmma_kernel<<<(N + 127) / 128, 512, SMEM_B>>>(x, N);
    {
        long long tot = (long long)E * 16;
        int blocks = (int)((tot + 255) / 256);
        scatter1_kernel<<<blocks, 256>>>(src, dst, E);
    }
    node1_kernel<<<(N + 255) / 256, 256>>>(b1l, W2l, W2r, N);
    scatter2_kernel<<<(E + 255) / 256, 256>>>(src, dst, E);
    node2_kernel<<<(N + 255) / 256, 256>>>(b2l, (float*)d_out, N);
}